// round 3
// baseline (speedup 1.0000x reference)
#include <cuda_runtime.h>
#include <cuda_bf16.h>
#include <mma.h>
#include <cstdint>
#include <cstdio>

using namespace nvcuda;

constexpr int N_TOK = 4096;
constexpr int DIM = 256;
constexpr int NUM_LAYERS = 20;
constexpr int NUM_HEADS = 200;
constexpr int ND = N_TOK * DIM;

// ---------------- static device scratch (no cudaMalloc allowed) ----------------
__device__ __nv_bfloat16 g_xbf[ND];                               // x in bf16
__device__ __nv_bfloat16 g_QKV[(size_t)NUM_HEADS * 3 * ND];       // [head][q/k/v][n][d], ~1.26 GB
__device__ float         g_O[(size_t)NUM_HEADS * ND];             // per-head attention out, ~839 MB
__device__ float         g_h[2 * ND];                             // MLP ping-pong

__device__ __forceinline__ float tanh_apx(float x) {
    float y; asm("tanh.approx.f32 %0, %1;" : "=f"(y) : "f"(x)); return y;
}
__device__ __forceinline__ float ex2_apx(float x) {
    float y; asm("ex2.approx.f32 %0, %1;" : "=f"(y) : "f"(x)); return y;
}

// ---------------- prep: x fp32 -> bf16 ----------------
__global__ void prep_kernel(const float* __restrict__ x) {
    int i = blockIdx.x * blockDim.x + threadIdx.x;
    g_xbf[i] = __float2bfloat16(x[i]);
}

// ---------------- QKV projection: C = x @ W^T + b  (bf16 out) ----------------
// grid (N/128, 2, 600); block 256. BM=128, BN=128, K=256.
constexpr int PROJ_SMEM = 135168;  // Xs[128][264]bf16 + Ws[128][264]bf16; Cs[128][132]f32 reuses Xs

__global__ __launch_bounds__(256) void proj_kernel(
    const float* __restrict__ Wq, const float* __restrict__ bq,
    const float* __restrict__ Wk, const float* __restrict__ bk,
    const float* __restrict__ Wv, const float* __restrict__ bv) {
    extern __shared__ char sm[];
    __nv_bfloat16* Xs = (__nv_bfloat16*)sm;             // [128][264]
    __nv_bfloat16* Ws = (__nv_bfloat16*)(sm + 67584);   // [128][264]
    float*         Cs = (float*)sm;                     // [128][132] (reuse)
    __shared__ float bias_s[128];

    const int tid = threadIdx.x;
    const int mat = blockIdx.z;          // 0..599
    const int head = mat / 3, w = mat % 3;
    const float* W    = (w == 0 ? Wq : (w == 1 ? Wk : Wv)) + (size_t)head * DIM * DIM;
    const float* bias = (w == 0 ? bq : (w == 1 ? bk : bv)) + head * DIM;
    const int n0 = blockIdx.x * 128;
    const int j0 = blockIdx.y * 128;

    if (tid < 128) bias_s[tid] = bias[j0 + tid];

    // load X tile [128,256] bf16 (uint4 = 8 bf16)
    for (int t = tid; t < 4096; t += 256) {
        int r = t >> 5, kc = (t & 31) << 3;
        *(uint4*)&Xs[r * 264 + kc] = *(const uint4*)&g_xbf[(size_t)(n0 + r) * DIM + kc];
    }
    // load W tile [128 rows j][256 k] fp32 -> bf16
    for (int t = tid; t < 8192; t += 256) {
        int j = t >> 6, kc = (t & 63) << 2;
        float4 v = *(const float4*)&W[(size_t)(j0 + j) * DIM + kc];
        __nv_bfloat162 h0 = __floats2bfloat162_rn(v.x, v.y);
        __nv_bfloat162 h1 = __floats2bfloat162_rn(v.z, v.w);
        *(__nv_bfloat162*)&Ws[j * 264 + kc]     = h0;
        *(__nv_bfloat162*)&Ws[j * 264 + kc + 2] = h1;
    }
    __syncthreads();

    const int wid = tid >> 5;
    const int wr = (wid & 3) * 32;   // row offset (n)
    const int wc = (wid >> 2) * 64;  // col offset (j)
    wmma::fragment<wmma::accumulator, 16, 16, 16, float> c[2][4];
#pragma unroll
    for (int i = 0; i < 2; i++)
#pragma unroll
        for (int j = 0; j < 4; j++) wmma::fill_fragment(c[i][j], 0.f);

#pragma unroll
    for (int kk = 0; kk < 16; kk++) {
        wmma::fragment<wmma::matrix_a, 16, 16, 16, __nv_bfloat16, wmma::row_major> a[2];
#pragma unroll
        for (int i = 0; i < 2; i++)
            wmma::load_matrix_sync(a[i], &Xs[(wr + i * 16) * 264 + kk * 16], 264);
        wmma::fragment<wmma::matrix_b, 16, 16, 16, __nv_bfloat16, wmma::col_major> b[4];
#pragma unroll
        for (int j = 0; j < 4; j++)
            wmma::load_matrix_sync(b[j], &Ws[(wc + j * 16) * 264 + kk * 16], 264);
#pragma unroll
        for (int i = 0; i < 2; i++)
#pragma unroll
            for (int j = 0; j < 4; j++)
                wmma::mma_sync(c[i][j], a[i], b[j], c[i][j]);
    }
    __syncthreads();  // done reading Xs before Cs overwrites it
#pragma unroll
    for (int i = 0; i < 2; i++)
#pragma unroll
        for (int j = 0; j < 4; j++)
            wmma::store_matrix_sync(&Cs[(wr + i * 16) * 132 + wc + j * 16], c[i][j], 132,
                                    wmma::mem_row_major);
    __syncthreads();

    __nv_bfloat16* out = g_QKV + ((size_t)mat * N_TOK + n0) * DIM + j0;
    for (int t = tid; t < 4096; t += 256) {
        int r = t >> 5, c0 = (t & 31) << 2;
        float4 v = *(float4*)&Cs[r * 132 + c0];
        v.x += bias_s[c0]; v.y += bias_s[c0 + 1]; v.z += bias_s[c0 + 2]; v.w += bias_s[c0 + 3];
        __nv_bfloat162 h0 = __floats2bfloat162_rn(v.x, v.y);
        __nv_bfloat162 h1 = __floats2bfloat162_rn(v.z, v.w);
        *(__nv_bfloat162*)&out[(size_t)r * DIM + c0]     = h0;
        *(__nv_bfloat162*)&out[(size_t)r * DIM + c0 + 2] = h1;
    }
}

// ---------------- fused attention (flash-style, per head) ----------------
// grid (N/64, 200); block 256; BM=64, BN=64.
// weights = softmax(sigmoid(qk/16)) == softmax(0.5*tanh(qk/32))  [shift invariance]
constexpr int OFF_Q = 0;        // bf16 [64][264]
constexpr int OFF_K = 33792;    // bf16 [64][264]
constexpr int OFF_V = 67584;    // bf16 [64][264]
constexpr int OFF_S = 101376;   // f32  [64][68]
constexpr int OFF_P = 118784;   // bf16 [64][72]
constexpr int OFF_RS = 128000;  // f32  [64]
constexpr int ATTN_SMEM = 128256;

__global__ __launch_bounds__(256) void attn_kernel() {
    extern __shared__ char sm[];
    __nv_bfloat16* Qs = (__nv_bfloat16*)(sm + OFF_Q);
    __nv_bfloat16* Ks = (__nv_bfloat16*)(sm + OFF_K);
    __nv_bfloat16* Vs = (__nv_bfloat16*)(sm + OFF_V);
    float*        Ssm = (float*)(sm + OFF_S);
    __nv_bfloat16* Ps = (__nv_bfloat16*)(sm + OFF_P);
    float*         rs = (float*)(sm + OFF_RS);
    float*        Osm = (float*)(sm + OFF_K);   // [64][260], reuses K+V region after loop

    const int tid = threadIdx.x;
    const int wid = tid >> 5;
    const int head = blockIdx.y;
    const int q0 = blockIdx.x * 64;
    const __nv_bfloat16* Qg = g_QKV + ((size_t)(head * 3 + 0) * N_TOK + q0) * DIM;
    const __nv_bfloat16* Kg = g_QKV + (size_t)(head * 3 + 1) * ND;
    const __nv_bfloat16* Vg = g_QKV + (size_t)(head * 3 + 2) * ND;

    for (int t = tid; t < 2048; t += 256) {
        int r = t >> 5, kc = (t & 31) << 3;
        *(uint4*)&Qs[r * 264 + kc] = *(const uint4*)&Qg[(size_t)r * DIM + kc];
    }
    if (tid < 64) rs[tid] = 0.f;

    const int sr = wid >> 1;   // 0..3 : 16-row band
    const int sc = wid & 1;    // 0..1 : S col-half (32) / O col-half (128)

    wmma::fragment<wmma::accumulator, 16, 16, 16, float> co[8];
#pragma unroll
    for (int f = 0; f < 8; f++) wmma::fill_fragment(co[f], 0.f);

    for (int kt = 0; kt < 64; kt++) {
        const int kb = kt * 64;
        __syncthreads();  // prev PV done with Ks/Vs
        for (int t = tid; t < 2048; t += 256) {
            int r = t >> 5, kc = (t & 31) << 3;
            *(uint4*)&Ks[r * 264 + kc] = *(const uint4*)&Kg[(size_t)(kb + r) * DIM + kc];
            *(uint4*)&Vs[r * 264 + kc] = *(const uint4*)&Vg[(size_t)(kb + r) * DIM + kc];
        }
        __syncthreads();

        // S = Q @ K^T : each warp 16x32
        wmma::fragment<wmma::accumulator, 16, 16, 16, float> cs[2];
        wmma::fill_fragment(cs[0], 0.f);
        wmma::fill_fragment(cs[1], 0.f);
#pragma unroll
        for (int kk = 0; kk < 16; kk++) {
            wmma::fragment<wmma::matrix_a, 16, 16, 16, __nv_bfloat16, wmma::row_major> af;
            wmma::load_matrix_sync(af, &Qs[(sr * 16) * 264 + kk * 16], 264);
#pragma unroll
            for (int f = 0; f < 2; f++) {
                wmma::fragment<wmma::matrix_b, 16, 16, 16, __nv_bfloat16, wmma::col_major> bf;
                wmma::load_matrix_sync(bf, &Ks[(sc * 32 + f * 16) * 264 + kk * 16], 264);
                wmma::mma_sync(cs[f], af, bf, cs[f]);
            }
        }
        wmma::store_matrix_sync(&Ssm[(sr * 16) * 68 + sc * 32],      cs[0], 68, wmma::mem_row_major);
        wmma::store_matrix_sync(&Ssm[(sr * 16) * 68 + sc * 32 + 16], cs[1], 68, wmma::mem_row_major);
        __syncthreads();

        // p = ex2(log2e * 0.5 * tanh(qk/32)); accumulate rowsum; P -> bf16
        {
            int r = tid >> 2, c0 = (tid & 3) * 16;
            float lsum = 0.f;
#pragma unroll
            for (int i = 0; i < 16; i += 4) {
                float4 v = *(float4*)&Ssm[r * 68 + c0 + i];
                float p0 = ex2_apx(0.72134752f * tanh_apx(0.03125f * v.x));
                float p1 = ex2_apx(0.72134752f * tanh_apx(0.03125f * v.y));
                float p2 = ex2_apx(0.72134752f * tanh_apx(0.03125f * v.z));
                float p3 = ex2_apx(0.72134752f * tanh_apx(0.03125f * v.w));
                lsum += (p0 + p1) + (p2 + p3);
                *(__nv_bfloat162*)&Ps[r * 72 + c0 + i]     = __floats2bfloat162_rn(p0, p1);
                *(__nv_bfloat162*)&Ps[r * 72 + c0 + i + 2] = __floats2bfloat162_rn(p2, p3);
            }
            lsum += __shfl_xor_sync(0xffffffffu, lsum, 1);
            lsum += __shfl_xor_sync(0xffffffffu, lsum, 2);
            if ((tid & 3) == 0) rs[r] += lsum;
        }
        __syncthreads();

        // O += P @ V : each warp 16x128
#pragma unroll
        for (int kk = 0; kk < 4; kk++) {
            wmma::fragment<wmma::matrix_a, 16, 16, 16, __nv_bfloat16, wmma::row_major> af;
            wmma::load_matrix_sync(af, &Ps[(sr * 16) * 72 + kk * 16], 72);
#pragma unroll
            for (int f = 0; f < 8; f++) {
                wmma::fragment<wmma::matrix_b, 16, 16, 16, __nv_bfloat16, wmma::row_major> bf;
                wmma::load_matrix_sync(bf, &Vs[(kk * 16) * 264 + sc * 128 + f * 16], 264);
                wmma::mma_sync(co[f], af, bf, co[f]);
            }
        }
    }
    __syncthreads();
#pragma unroll
    for (int f = 0; f < 8; f++)
        wmma::store_matrix_sync(&Osm[(sr * 16) * 260 + sc * 128 + f * 16], co[f], 260,
                                wmma::mem_row_major);
    __syncthreads();
    {
        int r = tid >> 2, c0 = (tid & 3) * 64;
        float inv = 1.0f / rs[r];
        float* Og = g_O + ((size_t)head * N_TOK + q0 + r) * DIM + c0;
#pragma unroll
        for (int i = 0; i < 64; i += 4) {
            float4 v = *(float4*)&Osm[r * 260 + c0 + i];
            v.x *= inv; v.y *= inv; v.z *= inv; v.w *= inv;
            *(float4*)&Og[i] = v;
        }
    }
}

// ---------------- mean over heads (deterministic, no atomics) ----------------
__global__ void reduce_kernel(float* __restrict__ out) {
    int i = blockIdx.x * blockDim.x + threadIdx.x;
    const float* p = g_O + i;
    float s = 0.f;
#pragma unroll 8
    for (int h = 0; h < NUM_HEADS; h++) s += p[(size_t)h * ND];
    out[i] = s * (1.0f / NUM_HEADS);
}

// ---------------- fp32 GEMM for MLP/final (precision-critical path) ----------------
// grid (N/64, D/64); block 256. mode 0: relu(A@B^T + b). mode 1: sigmoid(A@B) + b.
__global__ __launch_bounds__(256) void gemm_fp32(
    const float* __restrict__ A, const float* __restrict__ B,
    const float* __restrict__ bias, float* __restrict__ C,
    int transB, int mode) {
    __shared__ float As[16][68];
    __shared__ float Bs[16][68];
    const int tid = threadIdx.x;
    const int n0 = blockIdx.x * 64;
    const int j0 = blockIdx.y * 64;
    const int r0 = (tid >> 4) * 4;
    const int c0 = (tid & 15) * 4;
    float acc[4][4];
#pragma unroll
    for (int i = 0; i < 4; i++)
#pragma unroll
        for (int j = 0; j < 4; j++) acc[i][j] = 0.f;

    for (int ko = 0; ko < DIM; ko += 16) {
        __syncthreads();
        {
            int k = tid & 15, n = tid >> 4;
#pragma unroll
            for (int p = 0; p < 4; p++)
                As[k][n + 16 * p] = A[(size_t)(n0 + n + 16 * p) * DIM + ko + k];
            if (transB) {
#pragma unroll
                for (int p = 0; p < 4; p++)
                    Bs[k][n + 16 * p] = B[(size_t)(j0 + n + 16 * p) * DIM + ko + k];
            } else {
                int j = tid & 63, kq = tid >> 6;
#pragma unroll
                for (int p = 0; p < 4; p++)
                    Bs[kq + 4 * p][j] = B[(size_t)(ko + kq + 4 * p) * DIM + j0 + j];
            }
        }
        __syncthreads();
#pragma unroll
        for (int kk = 0; kk < 16; kk++) {
            float4 a = *(const float4*)&As[kk][r0];
            float4 b = *(const float4*)&Bs[kk][c0];
            float av[4] = {a.x, a.y, a.z, a.w};
            float bv[4] = {b.x, b.y, b.z, b.w};
#pragma unroll
            for (int i = 0; i < 4; i++)
#pragma unroll
                for (int j = 0; j < 4; j++) acc[i][j] += av[i] * bv[j];
        }
    }
#pragma unroll
    for (int i = 0; i < 4; i++) {
        int n = n0 + r0 + i;
        float4 v;
        float* vp = &v.x;
#pragma unroll
        for (int j = 0; j < 4; j++) {
            int cidx = j0 + c0 + j;
            float t = acc[i][j];
            if (mode == 0) { t += bias[cidx]; t = t > 0.f ? t : 0.f; }
            else           { t = 1.f / (1.f + expf(-t)) + bias[cidx]; }
            vp[j] = t;
        }
        *(float4*)&C[(size_t)n * DIM + j0 + c0] = v;
    }
}

// ---------------- launch ----------------
extern "C" void kernel_launch(void* const* d_in, const int* in_sizes, int n_in,
                              void* d_out, int out_size) {
    const float* x  = (const float*)d_in[0];
    const float* Wq = (const float*)d_in[1];
    const float* bq = (const float*)d_in[2];
    const float* Wk = (const float*)d_in[3];
    const float* bk = (const float*)d_in[4];
    const float* Wv = (const float*)d_in[5];
    const float* bv = (const float*)d_in[6];
    const float* Wl = (const float*)d_in[7];
    const float* bl = (const float*)d_in[8];
    const float* fw = (const float*)d_in[9];
    const float* fb = (const float*)d_in[10];

    cudaFuncSetAttribute(proj_kernel, cudaFuncAttributeMaxDynamicSharedMemorySize, PROJ_SMEM);
    cudaFuncSetAttribute(attn_kernel, cudaFuncAttributeMaxDynamicSharedMemorySize, ATTN_SMEM);

    float* hbuf = nullptr;
    cudaGetSymbolAddress((void**)&hbuf, g_h);

    prep_kernel<<<ND / 256, 256>>>(x);
    proj_kernel<<<dim3(N_TOK / 128, 2, 3 * NUM_HEADS), 256, PROJ_SMEM>>>(Wq, bq, Wk, bk, Wv, bv);
    attn_kernel<<<dim3(N_TOK / 64, NUM_HEADS), 256, ATTN_SMEM>>>();
    reduce_kernel<<<ND / 256, 256>>>(hbuf);

    for (int l = 0; l < NUM_LAYERS; l++) {
        gemm_fp32<<<dim3(N_TOK / 64, DIM / 64), 256>>>(
            hbuf + (size_t)(l & 1) * ND, Wl + (size_t)l * DIM * DIM, bl + l * DIM,
            hbuf + (size_t)((l + 1) & 1) * ND, 1, 0);
    }
    gemm_fp32<<<dim3(N_TOK / 64, DIM / 64), 256>>>(hbuf, fw, fb, (float*)d_out, 0, 1);
}

// round 8
// speedup vs baseline: 2.1800x; 2.1800x over previous
#include <cuda_runtime.h>
#include <cuda_bf16.h>
#include <mma.h>
#include <cstdint>
#include <cstdio>

using namespace nvcuda;

constexpr int N_TOK = 4096;
constexpr int DIM = 256;
constexpr int NUM_LAYERS = 20;
constexpr int NUM_HEADS = 200;
constexpr int ND = N_TOK * DIM;

// ---------------- static device scratch (no cudaMalloc allowed) ----------------
__device__ __nv_bfloat16 g_xbf[ND];                               // x in bf16
__device__ __nv_bfloat16 g_QKV[(size_t)NUM_HEADS * 3 * ND];       // [head][q/k/v][n][d]
__device__ float         g_O[(size_t)NUM_HEADS * ND];             // per-head attention out
__device__ float         g_h[2 * ND];                             // MLP ping-pong

__device__ __forceinline__ float tanh_apx(float x) {
    float y; asm("tanh.approx.f32 %0, %1;" : "=f"(y) : "f"(x)); return y;
}
__device__ __forceinline__ float ex2_apx(float x) {
    float y; asm("ex2.approx.f32 %0, %1;" : "=f"(y) : "f"(x)); return y;
}
__device__ __forceinline__ uint32_t pack_bf16(float lo, float hi) {
    uint32_t r; asm("cvt.rn.satfinite.bf16x2.f32 %0, %1, %2;" : "=r"(r) : "f"(hi), "f"(lo));
    return r;
}
__device__ __forceinline__ uint32_t smem_to_u32(const void* p) {
    uint32_t a;
    asm("{ .reg .u64 t; cvta.to.shared.u64 t, %1; cvt.u32.u64 %0, t; }" : "=r"(a) : "l"(p));
    return a;
}

// ---- baseline-PTX building blocks (no sm_103a features) ----
__device__ __forceinline__ void mma16816(float* c, const uint32_t* a, uint32_t b0, uint32_t b1) {
    asm volatile(
        "mma.sync.aligned.m16n8k16.row.col.f32.bf16.bf16.f32 "
        "{%0,%1,%2,%3}, {%4,%5,%6,%7}, {%8,%9}, {%0,%1,%2,%3};"
        : "+f"(c[0]), "+f"(c[1]), "+f"(c[2]), "+f"(c[3])
        : "r"(a[0]), "r"(a[1]), "r"(a[2]), "r"(a[3]), "r"(b0), "r"(b1));
}
__device__ __forceinline__ void ldsm4(uint32_t* r, uint32_t addr) {
    asm volatile("ldmatrix.sync.aligned.m8n8.x4.shared.b16 {%0,%1,%2,%3}, [%4];"
                 : "=r"(r[0]), "=r"(r[1]), "=r"(r[2]), "=r"(r[3]) : "r"(addr));
}
__device__ __forceinline__ void ldsm4t(uint32_t* r, uint32_t addr) {
    asm volatile("ldmatrix.sync.aligned.m8n8.x4.trans.shared.b16 {%0,%1,%2,%3}, [%4];"
                 : "=r"(r[0]), "=r"(r[1]), "=r"(r[2]), "=r"(r[3]) : "r"(addr));
}
#define CP_ASYNC16(dst, src) \
    asm volatile("cp.async.cg.shared.global [%0], [%1], 16;" :: "r"(dst), "l"(src))
#define CP_COMMIT() asm volatile("cp.async.commit_group;" ::: "memory")
#define CP_WAIT1() asm volatile("cp.async.wait_group 1;" ::: "memory")
#define CP_WAIT0() asm volatile("cp.async.wait_group 0;" ::: "memory")

// ---------------- prep: x fp32 -> bf16 ----------------
__global__ void prep_kernel(const float* __restrict__ x) {
    int i = blockIdx.x * blockDim.x + threadIdx.x;
    g_xbf[i] = __float2bfloat16(x[i]);
}

// ---------------- QKV projection: C = x @ W^T + b  (bf16 out, row-major) ----------------
constexpr int PROJ_SMEM = 135168;

__global__ __launch_bounds__(256) void proj_kernel(
    const float* __restrict__ Wq, const float* __restrict__ bq,
    const float* __restrict__ Wk, const float* __restrict__ bk,
    const float* __restrict__ Wv, const float* __restrict__ bv) {
    extern __shared__ char sm[];
    __nv_bfloat16* Xs = (__nv_bfloat16*)sm;             // [128][264]
    __nv_bfloat16* Ws = (__nv_bfloat16*)(sm + 67584);   // [128][264]
    float*         Cs = (float*)sm;                     // [128][132] (reuse)
    __shared__ float bias_s[128];

    const int tid = threadIdx.x;
    const int mat = blockIdx.z;
    const int head = mat / 3, w = mat % 3;
    const float* W    = (w == 0 ? Wq : (w == 1 ? Wk : Wv)) + (size_t)head * DIM * DIM;
    const float* bias = (w == 0 ? bq : (w == 1 ? bk : bv)) + head * DIM;
    const int n0 = blockIdx.x * 128;
    const int j0 = blockIdx.y * 128;

    if (tid < 128) bias_s[tid] = bias[j0 + tid];

    for (int t = tid; t < 4096; t += 256) {
        int r = t >> 5, kc = (t & 31) << 3;
        *(uint4*)&Xs[r * 264 + kc] = *(const uint4*)&g_xbf[(size_t)(n0 + r) * DIM + kc];
    }
    for (int t = tid; t < 8192; t += 256) {
        int j = t >> 6, kc = (t & 63) << 2;
        float4 v = *(const float4*)&W[(size_t)(j0 + j) * DIM + kc];
        *(__nv_bfloat162*)&Ws[j * 264 + kc]     = __floats2bfloat162_rn(v.x, v.y);
        *(__nv_bfloat162*)&Ws[j * 264 + kc + 2] = __floats2bfloat162_rn(v.z, v.w);
    }
    __syncthreads();

    const int wid = tid >> 5;
    const int wr = (wid & 3) * 32;
    const int wc = (wid >> 2) * 64;
    wmma::fragment<wmma::accumulator, 16, 16, 16, float> c[2][4];
#pragma unroll
    for (int i = 0; i < 2; i++)
#pragma unroll
        for (int j = 0; j < 4; j++) wmma::fill_fragment(c[i][j], 0.f);

#pragma unroll
    for (int kk = 0; kk < 16; kk++) {
        wmma::fragment<wmma::matrix_a, 16, 16, 16, __nv_bfloat16, wmma::row_major> a[2];
#pragma unroll
        for (int i = 0; i < 2; i++)
            wmma::load_matrix_sync(a[i], &Xs[(wr + i * 16) * 264 + kk * 16], 264);
        wmma::fragment<wmma::matrix_b, 16, 16, 16, __nv_bfloat16, wmma::col_major> b[4];
#pragma unroll
        for (int j = 0; j < 4; j++)
            wmma::load_matrix_sync(b[j], &Ws[(wc + j * 16) * 264 + kk * 16], 264);
#pragma unroll
        for (int i = 0; i < 2; i++)
#pragma unroll
            for (int j = 0; j < 4; j++)
                wmma::mma_sync(c[i][j], a[i], b[j], c[i][j]);
    }
    __syncthreads();
#pragma unroll
    for (int i = 0; i < 2; i++)
#pragma unroll
        for (int j = 0; j < 4; j++)
            wmma::store_matrix_sync(&Cs[(size_t)(wr + i * 16) * 132 + wc + j * 16],
                                    c[i][j], 132, wmma::mem_row_major);
    __syncthreads();

    __nv_bfloat16* out = g_QKV + ((size_t)mat * N_TOK + n0) * DIM + j0;
    for (int t = tid; t < 4096; t += 256) {
        int r = t >> 5, c0 = (t & 31) << 2;
        float4 v = *(float4*)&Cs[r * 132 + c0];
        v.x += bias_s[c0]; v.y += bias_s[c0 + 1]; v.z += bias_s[c0 + 2]; v.w += bias_s[c0 + 3];
        *(__nv_bfloat162*)&out[(size_t)r * DIM + c0]     = __floats2bfloat162_rn(v.x, v.y);
        *(__nv_bfloat162*)&out[(size_t)r * DIM + c0 + 2] = __floats2bfloat162_rn(v.z, v.w);
    }
}

// ================= FA2-style fused flash attention (mma.sync) =================
// BM=128 q rows/CTA, 8 warps x 16 rows, BN=64 keys/tile, full d=256 in regs.
// S lives in C-fragments; softmax in regs; C-frag == A-frag layout => direct PV.
constexpr int Q_OFF = 0;        // bf16 [128][264]
constexpr int K_OFF = 67584;    // 2 stages x bf16 [64][264]
constexpr int V_OFF = 135168;   // 2 stages x bf16 [64][264]
constexpr int KV_STAGE = 33792;
constexpr int ATTN_SMEM = 202752;

__global__ __launch_bounds__(256, 1) void attn_kernel() {
    extern __shared__ char sm[];
    const uint32_t sbase = smem_to_u32(sm);
    const int tid = threadIdx.x, wid = tid >> 5, lane = tid & 31;
    const int head = blockIdx.y;
    const int q0 = blockIdx.x * 128;
    const __nv_bfloat16* Qg = g_QKV + (size_t)(head * 3 + 0) * ND + (size_t)q0 * DIM;
    const __nv_bfloat16* Kg = g_QKV + (size_t)(head * 3 + 1) * ND;
    const __nv_bfloat16* Vg = g_QKV + (size_t)(head * 3 + 2) * ND;

    // Q -> smem (row-major, stride 264 halves)
    for (int t = tid; t < 4096; t += 256) {
        int r = t >> 5, c = (t & 31) << 3;
        *(uint4*)(sm + Q_OFF + (r * 264 + c) * 2) = *(const uint4*)&Qg[(size_t)r * DIM + c];
    }

    // cp.async K/V tile loader: 64 rows x 512B, 16B chunks, 8 per thread each
    auto issueKV = [&](int kt, int stage) {
        const char* Ks = (const char*)(Kg + (size_t)kt * 64 * DIM);
        const char* Vs = (const char*)(Vg + (size_t)kt * 64 * DIM);
        uint32_t kd = sbase + K_OFF + stage * KV_STAGE;
        uint32_t vd = sbase + V_OFF + stage * KV_STAGE;
#pragma unroll
        for (int i = 0; i < 8; i++) {
            int t = tid + i * 256;
            int row = t >> 5, c = t & 31;
            uint32_t doff = row * 528 + c * 16;
            CP_ASYNC16(kd + doff, Ks + row * 512 + c * 16);
            CP_ASYNC16(vd + doff, Vs + row * 512 + c * 16);
        }
    };
    issueKV(0, 0); CP_COMMIT();
    issueKV(1, 1); CP_COMMIT();

    // per-lane ldmatrix byte offsets (within a tile)
    const int r0 = wid * 16;
    const uint32_t qa = sbase + Q_OFF + (uint32_t)(r0 + (lane & 15)) * 528 + ((lane >> 4) << 4);
    const uint32_t ka = (uint32_t)((lane & 7) + ((lane >> 4) << 3)) * 528 + (((lane >> 3) & 1) << 4);
    const uint32_t va = (uint32_t)((lane & 7) + (((lane >> 3) & 1) << 3)) * 528 + ((lane >> 4) << 4);

    float o[128];
#pragma unroll
    for (int i = 0; i < 128; i++) o[i] = 0.f;
    float rsum0 = 0.f, rsum1 = 0.f;

    for (int kt = 0; kt < 64; kt++) {
        if (kt < 63) { CP_WAIT1(); } else { CP_WAIT0(); }
        __syncthreads();
        const uint32_t Kst = sbase + K_OFF + (kt & 1) * KV_STAGE;
        const uint32_t Vst = sbase + V_OFF + (kt & 1) * KV_STAGE;

        // ---- S = Q @ K^T (16x64 per warp, K=256) ----
        float s[32];
#pragma unroll
        for (int i = 0; i < 32; i++) s[i] = 0.f;
#pragma unroll
        for (int kk = 0; kk < 16; kk++) {
            uint32_t a[4];
            ldsm4(a, qa + kk * 32);
#pragma unroll
            for (int np = 0; np < 4; np++) {
                uint32_t b[4];
                ldsm4(b, Kst + ka + np * 8448 + kk * 32);
                mma16816(&s[np * 8], a, b[0], b[1]);
                mma16816(&s[np * 8 + 4], a, b[2], b[3]);
            }
        }
        // ---- softmax numerator: p = ex2(log2e*0.5*tanh(s/32)); partial rowsums ----
#pragma unroll
        for (int n = 0; n < 8; n++) {
            float p0 = ex2_apx(0.72134752f * tanh_apx(0.03125f * s[n * 4 + 0]));
            float p1 = ex2_apx(0.72134752f * tanh_apx(0.03125f * s[n * 4 + 1]));
            float p2 = ex2_apx(0.72134752f * tanh_apx(0.03125f * s[n * 4 + 2]));
            float p3 = ex2_apx(0.72134752f * tanh_apx(0.03125f * s[n * 4 + 3]));
            rsum0 += p0 + p1; rsum1 += p2 + p3;
            s[n * 4 + 0] = p0; s[n * 4 + 1] = p1; s[n * 4 + 2] = p2; s[n * 4 + 3] = p3;
        }
        // ---- pack P into A-fragments (C-frag layout == A-frag layout) ----
        uint32_t pk[16];
#pragma unroll
        for (int kk = 0; kk < 4; kk++) {
            pk[kk * 4 + 0] = pack_bf16(s[kk * 8 + 0], s[kk * 8 + 1]);
            pk[kk * 4 + 1] = pack_bf16(s[kk * 8 + 2], s[kk * 8 + 3]);
            pk[kk * 4 + 2] = pack_bf16(s[kk * 8 + 4], s[kk * 8 + 5]);
            pk[kk * 4 + 3] = pack_bf16(s[kk * 8 + 6], s[kk * 8 + 7]);
        }
        // ---- O += P @ V (16x256 per warp, k=64) ----
#pragma unroll
        for (int kk = 0; kk < 4; kk++) {
#pragma unroll
            for (int np = 0; np < 16; np++) {
                uint32_t b[4];
                ldsm4t(b, Vst + va + kk * 8448 + np * 32);
                mma16816(&o[np * 8], &pk[kk * 4], b[0], b[1]);
                mma16816(&o[np * 8 + 4], &pk[kk * 4], b[2], b[3]);
            }
        }
        if (kt < 62) {
            __syncthreads();
            issueKV(kt + 2, kt & 1);
            CP_COMMIT();
        }
    }

    // ---- finalize: complete row sums across the quad, normalize, store ----
    rsum0 += __shfl_xor_sync(0xffffffffu, rsum0, 1);
    rsum0 += __shfl_xor_sync(0xffffffffu, rsum0, 2);
    rsum1 += __shfl_xor_sync(0xffffffffu, rsum1, 1);
    rsum1 += __shfl_xor_sync(0xffffffffu, rsum1, 2);
    float inv0 = 1.0f / rsum0, inv1 = 1.0f / rsum1;

    const int row = q0 + r0 + (lane >> 2);
    const int colb = (lane & 3) * 2;
    float* O0 = g_O + (size_t)head * ND + (size_t)row * DIM;
    float* O1 = O0 + 8 * DIM;
#pragma unroll
    for (int n = 0; n < 32; n++) {
        float2 v0 = make_float2(o[n * 4 + 0] * inv0, o[n * 4 + 1] * inv0);
        float2 v1 = make_float2(o[n * 4 + 2] * inv1, o[n * 4 + 3] * inv1);
        *(float2*)&O0[n * 8 + colb] = v0;
        *(float2*)&O1[n * 8 + colb] = v1;
    }
}

// ---------------- mean over heads (deterministic, no atomics) ----------------
__global__ void reduce_kernel(float* __restrict__ out) {
    int i = blockIdx.x * blockDim.x + threadIdx.x;
    const float* p = g_O + i;
    float s = 0.f;
#pragma unroll 8
    for (int h = 0; h < NUM_HEADS; h++) s += p[(size_t)h * ND];
    out[i] = s * (1.0f / NUM_HEADS);
}

// ---------------- fp32 GEMM for MLP/final (precision-critical path) ----------------
__global__ __launch_bounds__(256) void gemm_fp32(
    const float* __restrict__ A, const float* __restrict__ B,
    const float* __restrict__ bias, float* __restrict__ C,
    int transB, int mode) {
    __shared__ float As[16][68];
    __shared__ float Bs[16][68];
    const int tid = threadIdx.x;
    const int n0 = blockIdx.x * 64;
    const int j0 = blockIdx.y * 64;
    const int r0 = (tid >> 4) * 4;
    const int c0 = (tid & 15) * 4;
    float acc[4][4];
#pragma unroll
    for (int i = 0; i < 4; i++)
#pragma unroll
        for (int j = 0; j < 4; j++) acc[i][j] = 0.f;

    for (int ko = 0; ko < DIM; ko += 16) {
        __syncthreads();
        {
            int k = tid & 15, n = tid >> 4;
#pragma unroll
            for (int p = 0; p < 4; p++)
                As[k][n + 16 * p] = A[(size_t)(n0 + n + 16 * p) * DIM + ko + k];
            if (transB) {
#pragma unroll
                for (int p = 0; p < 4; p++)
                    Bs[k][n + 16 * p] = B[(size_t)(j0 + n + 16 * p) * DIM + ko + k];
            } else {
                int j = tid & 63, kq = tid >> 6;
#pragma unroll
                for (int p = 0; p < 4; p++)
                    Bs[kq + 4 * p][j] = B[(size_t)(ko + kq + 4 * p) * DIM + j0 + j];
            }
        }
        __syncthreads();
#pragma unroll
        for (int kk = 0; kk < 16; kk++) {
            float4 a = *(const float4*)&As[kk][r0];
            float4 b = *(const float4*)&Bs[kk][c0];
            float av[4] = {a.x, a.y, a.z, a.w};
            float bv[4] = {b.x, b.y, b.z, b.w};
#pragma unroll
            for (int i = 0; i < 4; i++)
#pragma unroll
                for (int j = 0; j < 4; j++) acc[i][j] += av[i] * bv[j];
        }
    }
#pragma unroll
    for (int i = 0; i < 4; i++) {
        int n = n0 + r0 + i;
        float4 v;
        float* vp = &v.x;
#pragma unroll
        for (int j = 0; j < 4; j++) {
            int cidx = j0 + c0 + j;
            float t = acc[i][j];
            if (mode == 0) { t += bias[cidx]; t = t > 0.f ? t : 0.f; }
            else           { t = 1.f / (1.f + expf(-t)) + bias[cidx]; }
            vp[j] = t;
        }
        *(float4*)&C[(size_t)n * DIM + j0 + c0] = v;
    }
}

// ---------------- launch ----------------
extern "C" void kernel_launch(void* const* d_in, const int* in_sizes, int n_in,
                              void* d_out, int out_size) {
    const float* x  = (const float*)d_in[0];
    const float* Wq = (const float*)d_in[1];
    const float* bq = (const float*)d_in[2];
    const float* Wk = (const float*)d_in[3];
    const float* bk = (const float*)d_in[4];
    const float* Wv = (const float*)d_in[5];
    const float* bv = (const float*)d_in[6];
    const float* Wl = (const float*)d_in[7];
    const float* bl = (const float*)d_in[8];
    const float* fw = (const float*)d_in[9];
    const float* fb = (const float*)d_in[10];

    cudaFuncSetAttribute(proj_kernel, cudaFuncAttributeMaxDynamicSharedMemorySize, PROJ_SMEM);
    cudaFuncSetAttribute(attn_kernel, cudaFuncAttributeMaxDynamicSharedMemorySize, ATTN_SMEM);

    float* hbuf = nullptr;
    cudaGetSymbolAddress((void**)&hbuf, g_h);

    prep_kernel<<<ND / 256, 256>>>(x);
    proj_kernel<<<dim3(N_TOK / 128, 2, 3 * NUM_HEADS), 256, PROJ_SMEM>>>(Wq, bq, Wk, bk, Wv, bv);
    attn_kernel<<<dim3(N_TOK / 128, NUM_HEADS), 256, ATTN_SMEM>>>();
    reduce_kernel<<<ND / 256, 256>>>(hbuf);

    for (int l = 0; l < NUM_LAYERS; l++) {
        gemm_fp32<<<dim3(N_TOK / 64, DIM / 64), 256>>>(
            hbuf + (size_t)(l & 1) * ND, Wl + (size_t)l * DIM * DIM, bl + l * DIM,
            hbuf + (size_t)((l + 1) & 1) * ND, 1, 0);
    }
    gemm_fp32<<<dim3(N_TOK / 64, DIM / 64), 256>>>(hbuf, fw, fb, (float*)d_out, 0, 1);
}